// round 17
// baseline (speedup 1.0000x reference)
#include <cuda_runtime.h>
#include <cuda_bf16.h>
#include <cstdint>
#include <cstddef>

#define HID   1024
#define NH    16
#define HD    64
#define BATCH 2
#define SEQ   2048
#define BH    (BATCH*NH)
#define MTOT  (BATCH*SEQ)

#define K_STAGE_B   36864u     /* attn p1: K tile 128 rows hi+lo           */
#define P2_STAGE_B  55296u     /* attn p2: P (36864) + V (18432)           */
#define QKV_STAGE_B 73728u     /* qkv: A hi/lo + B hi/lo, 128 rows each    */
#define ATTN_DSMEM  (3*P2_STAGE_B)   /* 165888 (>= 36864+3*36864=147456)   */
#define QKV_DSMEM   (3*QKV_STAGE_B)  /* 221184                             */

// hi/lo split-bf16 stored as separate arrays (pure-copy staging)
__device__ __align__(16) __nv_bfloat16 g_Xh[(size_t)MTOT * HID];
__device__ __align__(16) __nv_bfloat16 g_Xl[(size_t)MTOT * HID];
__device__ __align__(16) __nv_bfloat16 g_Wh[3][(size_t)HID * HID];
__device__ __align__(16) __nv_bfloat16 g_Wl[3][(size_t)HID * HID];
__device__ __align__(16) __nv_bfloat16 g_QKVh[3][(size_t)BH * SEQ * HD];
__device__ __align__(16) __nv_bfloat16 g_QKVl[3][(size_t)BH * SEQ * HD];

__device__ __forceinline__ void split2(float a, float b, uint32_t& hw, uint32_t& lw) {
    __nv_bfloat16 ha = __float2bfloat16(a), hb = __float2bfloat16(b);
    hw = (uint32_t)__bfloat16_as_ushort(ha) | ((uint32_t)__bfloat16_as_ushort(hb) << 16);
    __nv_bfloat16 la = __float2bfloat16(a - __bfloat162float(ha));
    __nv_bfloat16 lb = __float2bfloat16(b - __bfloat162float(hb));
    lw = (uint32_t)__bfloat16_as_ushort(la) | ((uint32_t)__bfloat16_as_ushort(lb) << 16);
}
__device__ __forceinline__ void mma_bf16(float* d, const uint32_t* a, const uint32_t* b) {
    asm volatile("mma.sync.aligned.m16n8k16.row.col.f32.bf16.bf16.f32 "
        "{%0,%1,%2,%3}, {%4,%5,%6,%7}, {%8,%9}, {%0,%1,%2,%3};\n"
        : "+f"(d[0]), "+f"(d[1]), "+f"(d[2]), "+f"(d[3])
        : "r"(a[0]), "r"(a[1]), "r"(a[2]), "r"(a[3]), "r"(b[0]), "r"(b[1]));
}
__device__ __forceinline__ void ldsm_x4(uint32_t* r, uint32_t a) {
    asm volatile("ldmatrix.sync.aligned.m8n8.x4.shared.b16 {%0,%1,%2,%3}, [%4];\n"
                 : "=r"(r[0]), "=r"(r[1]), "=r"(r[2]), "=r"(r[3]) : "r"(a));
}
__device__ __forceinline__ void ldsm_x4_t(uint32_t* r, uint32_t a) {
    asm volatile("ldmatrix.sync.aligned.m8n8.x4.trans.shared.b16 {%0,%1,%2,%3}, [%4];\n"
                 : "=r"(r[0]), "=r"(r[1]), "=r"(r[2]), "=r"(r[3]) : "r"(a));
}
__device__ __forceinline__ void cp16(uint32_t dst, const void* src) {
    asm volatile("cp.async.cg.shared.global [%0], [%1], 16;\n" :: "r"(dst), "l"(src));
}
#define CP_COMMIT() asm volatile("cp.async.commit_group;\n")
#define CP_WAIT1()  asm volatile("cp.async.wait_group 1;\n")
#define CP_WAIT0()  asm volatile("cp.async.wait_all;\n")

// ---------------- fp32 -> hi/lo bf16 (X + 3 W in one launch) ----------------
__global__ __launch_bounds__(256) void split_all_kernel(
    const float* __restrict__ X,  const float* __restrict__ Wq,
    const float* __restrict__ Wk, const float* __restrict__ Wv)
{
    const int nX4 = MTOT * HID / 4;
    const int nW4 = HID * HID / 4;
    int i = blockIdx.x * 256 + threadIdx.x;
    const float* src; __nv_bfloat16 *dh, *dl; int off;
    if (i < nX4) { src = X; dh = g_Xh; dl = g_Xl; off = i; }
    else {
        int j = i - nX4;
        int w = j / nW4; off = j - w * nW4;
        src = (w == 0) ? Wq : (w == 1) ? Wk : Wv;
        dh = g_Wh[w]; dl = g_Wl[w];
    }
    float4 v = ((const float4*)src)[off];
    uint32_t h0, l0, h1, l1;
    split2(v.x, v.y, h0, l0);
    split2(v.z, v.w, h1, l1);
    *(uint2*)(dh + (size_t)off*4) = make_uint2(h0, h1);
    *(uint2*)(dl + (size_t)off*4) = make_uint2(l0, l1);
}

// ------------- QKV GEMM: 128x128 block, warp 32x64, 3-stage cp.async --------
__global__ __launch_bounds__(256, 1) void qkv_t_kernel(
    const float* __restrict__ bq, const float* __restrict__ bk, const float* __restrict__ bv)
{
    extern __shared__ __align__(16) uint32_t dsm[];
    __shared__ float sBias[128];
    const int tid = threadIdx.x, lane = tid & 31, wid = tid >> 5;
    const int z = blockIdx.z, n0 = blockIdx.x * 128, m0 = blockIdx.y * 128;
    const int wm = wid & 3, wn = wid >> 2;
    const float* bias = (z == 0) ? bq : (z == 1) ? bk : bv;
    if (tid < 128) sBias[tid] = bias[n0 + tid];

    const char* XhG = (const char*)g_Xh;
    const char* XlG = (const char*)g_Xl;
    const char* WhG = (const char*)g_Wh[z];
    const char* WlG = (const char*)g_Wl[z];
    const uint32_t dbase = (uint32_t)__cvta_generic_to_shared(dsm);

    const int srow8 = tid >> 3, sc16 = tid & 7;
    auto issueXW = [&](int k, int s) {
        #pragma unroll
        for (int p = 0; p < 4; p++) {
            const int row = srow8 + p*32;
            const uint32_t d = dbase + (uint32_t)s*QKV_STAGE_B + row*144 + sc16*16;
            const size_t xo = (size_t)(m0+row)*2048 + k*128 + sc16*16;
            const size_t wo = (size_t)(n0+row)*2048 + k*128 + sc16*16;
            cp16(d,         XhG + xo);
            cp16(d + 18432, XlG + xo);
            cp16(d + 36864, WhG + wo);
            cp16(d + 55296, WlG + wo);
        }
    };

    float acc[2][8][4];
    #pragma unroll
    for (int mf = 0; mf < 2; mf++)
        #pragma unroll
        for (int nf = 0; nf < 8; nf++)
            #pragma unroll
            for (int j = 0; j < 4; j++) acc[mf][nf][j] = 0.f;

    const uint32_t a_base = (uint32_t)((lane & 7) + ((lane >> 3) & 1)*8)*144
                          + ((lane >> 4) & 1)*16;
    const uint32_t b_base = (uint32_t)(((lane >> 4) & 1)*8 + (lane & 7))*144
                          + ((lane >> 3) & 1)*16;

    issueXW(0, 0); CP_COMMIT();
    issueXW(1, 1); CP_COMMIT();

    for (int k = 0; k < 16; k++) {
        CP_WAIT1();
        __syncthreads();
        if (k + 2 < 16) issueXW(k + 2, (k + 2) % 3);
        CP_COMMIT();
        const uint32_t XhB = dbase + (uint32_t)(k % 3)*QKV_STAGE_B;
        const uint32_t XlB = XhB + 18432, WhB = XhB + 36864, WlB = XhB + 55296;
        #pragma unroll
        for (int kc = 0; kc < 4; kc++) {
            uint32_t Ah[2][4], Al[2][4];
            #pragma unroll
            for (int mf = 0; mf < 2; mf++) {
                const uint32_t ao = a_base + (uint32_t)(wm*32 + mf*16)*144 + kc*32;
                ldsm_x4(Ah[mf], XhB + ao);
                ldsm_x4(Al[mf], XlB + ao);
            }
            #pragma unroll
            for (int g = 0; g < 4; g++) {
                uint32_t Bh[4], Bl[4];
                const uint32_t boff = b_base + (uint32_t)(wn*64 + g*16)*144 + kc*32;
                ldsm_x4(Bh, WhB + boff);
                ldsm_x4(Bl, WlB + boff);
                #pragma unroll
                for (int mf = 0; mf < 2; mf++) {
                    mma_bf16(acc[mf][2*g],   Ah[mf], Bh);   mma_bf16(acc[mf][2*g],   Ah[mf], Bl);
                    mma_bf16(acc[mf][2*g],   Al[mf], Bh);
                    mma_bf16(acc[mf][2*g+1], Ah[mf], Bh+2); mma_bf16(acc[mf][2*g+1], Ah[mf], Bl+2);
                    mma_bf16(acc[mf][2*g+1], Al[mf], Bh+2);
                }
            }
        }
    }
    const float qs = (z == 0) ? 0.125f : 1.0f;
    #pragma unroll
    for (int mf = 0; mf < 2; mf++) {
        #pragma unroll
        for (int nf = 0; nf < 8; nf++) {
            const int nl = wn*64 + nf*8 + (lane & 3)*2, n = n0 + nl;
            const int h = n >> 6, d = n & 63;
            const float b0 = sBias[nl], b1 = sBias[nl+1];
            #pragma unroll
            for (int half = 0; half < 2; half++) {
                const int m = m0 + wm*32 + mf*16 + (lane >> 2) + half*8;
                const int bb = m >> 11, ss = m & (SEQ-1);
                const size_t ofs = ((size_t)(bb*NH+h)*SEQ + ss)*HD + d;
                uint32_t hw, lw;
                split2((acc[mf][nf][half*2] + b0)*qs, (acc[mf][nf][half*2+1] + b1)*qs, hw, lw);
                *(uint32_t*)(g_QKVh[z] + ofs) = hw;
                *(uint32_t*)(g_QKVl[z] + ofs) = lw;
            }
        }
    }
}

// ---- fused attention: 128q blocks; p1 warp 32qx64k (Q in regs), p2 32qx32d --
__global__ __launch_bounds__(256, 1) void attn_fused_kernel(
    float* __restrict__ ctx_out, float* __restrict__ Sbuf_all)
{
    extern __shared__ __align__(16) uint32_t dsm[];
    __shared__ float2 sMS[128][2];
    __shared__ float2 sFin[128];
    const int tid = threadIdx.x, lane = tid & 31, wid = tid >> 5;
    const int bh = blockIdx.y, q0 = blockIdx.x * 128;
    const int b = bh >> 4, h = bh & 15;
    const int wq = wid & 3, wk = wid >> 2;
    const char* QhG = (const char*)g_QKVh[0] + ((size_t)bh*SEQ + q0)*HD*2;
    const char* QlG = (const char*)g_QKVl[0] + ((size_t)bh*SEQ + q0)*HD*2;
    const char* KhG = (const char*)g_QKVh[1] + (size_t)bh*SEQ*HD*2;
    const char* KlG = (const char*)g_QKVl[1] + (size_t)bh*SEQ*HD*2;
    const char* VhG = (const char*)g_QKVh[2] + (size_t)bh*SEQ*HD*2;
    const char* VlG = (const char*)g_QKVl[2] + (size_t)bh*SEQ*HD*2;
    float* Sbuf = Sbuf_all + ((size_t)bh*SEQ + q0)*SEQ;

    const uint32_t dbase = (uint32_t)__cvta_generic_to_shared(dsm);
    const int srow8 = tid >> 3, sc16 = tid & 7;
    const int srow  = tid >> 4, sq4  = tid & 15;

    // -------- stage Q (128 rows, hi at 0 / lo at +18432), blocking --------
    #pragma unroll
    for (int p = 0; p < 4; p++) {
        const int row = srow8 + p*32;
        const uint32_t d = dbase + row*144 + sc16*16;
        cp16(d,         QhG + (size_t)row*128 + sc16*16);
        cp16(d + 18432, QlG + (size_t)row*128 + sc16*16);
    }
    CP_COMMIT(); CP_WAIT0();
    __syncthreads();

    const uint32_t a_base = (uint32_t)((lane & 7) + ((lane >> 3) & 1)*8)*144
                          + ((lane >> 4) & 1)*16;
    uint32_t Ah[2][4][4], Al[2][4][4];
    #pragma unroll
    for (int mf = 0; mf < 2; mf++)
        #pragma unroll
        for (int kc = 0; kc < 4; kc++) {
            const uint32_t ao = a_base + (uint32_t)(wq*32 + mf*16)*144 + kc*32;
            ldsm_x4(Ah[mf][kc], dbase + ao);
            ldsm_x4(Al[mf][kc], dbase + 18432 + ao);
        }

    // -------- phase 1: K pipeline (stages at 36864 + s*36864) --------
    auto issueK = [&](int kt, int s) {
        #pragma unroll
        for (int p = 0; p < 4; p++) {
            const int row = srow8 + p*32;
            const uint32_t d = dbase + 36864 + (uint32_t)s*K_STAGE_B + row*144 + sc16*16;
            const size_t ko = (size_t)(kt*128 + row)*128 + sc16*16;
            cp16(d,         KhG + ko);
            cp16(d + 18432, KlG + ko);
        }
    };
    const uint32_t b_base = (uint32_t)(((lane >> 4) & 1)*8 + (lane & 7))*144
                          + ((lane >> 3) & 1)*16;

    issueK(0, 0); CP_COMMIT();
    issueK(1, 1); CP_COMMIT();

    float mr[2][2], sr[2][2];
    #pragma unroll
    for (int mf = 0; mf < 2; mf++) { mr[mf][0]=mr[mf][1]=-1e30f; sr[mf][0]=sr[mf][1]=0.f; }

    for (int kt = 0; kt < 16; kt++) {
        CP_WAIT1();
        __syncthreads();
        if (kt + 2 < 16) issueK(kt + 2, (kt + 2) % 3);
        CP_COMMIT();
        const uint32_t KhB = dbase + 36864 + (uint32_t)(kt % 3)*K_STAGE_B;
        const uint32_t KlB = KhB + 18432;

        float acc[2][8][4];
        #pragma unroll
        for (int mf = 0; mf < 2; mf++)
            #pragma unroll
            for (int nf = 0; nf < 8; nf++)
                #pragma unroll
                for (int j = 0; j < 4; j++) acc[mf][nf][j] = 0.f;

        #pragma unroll
        for (int kc = 0; kc < 4; kc++) {
            #pragma unroll
            for (int g = 0; g < 4; g++) {
                uint32_t Bh[4], Bl[4];
                const uint32_t boff = b_base + (uint32_t)(wk*64 + g*16)*144 + kc*32;
                ldsm_x4(Bh, KhB + boff);
                ldsm_x4(Bl, KlB + boff);
                #pragma unroll
                for (int mf = 0; mf < 2; mf++) {
                    mma_bf16(acc[mf][2*g],   Ah[mf][kc], Bh);   mma_bf16(acc[mf][2*g],   Ah[mf][kc], Bl);
                    mma_bf16(acc[mf][2*g],   Al[mf][kc], Bh);
                    mma_bf16(acc[mf][2*g+1], Ah[mf][kc], Bh+2); mma_bf16(acc[mf][2*g+1], Ah[mf][kc], Bl+2);
                    mma_bf16(acc[mf][2*g+1], Al[mf][kc], Bh+2);
                }
            }
        }
        #pragma unroll
        for (int mf = 0; mf < 2; mf++) {
            const int r0 = wq*32 + mf*16 + (lane >> 2);
            #pragma unroll
            for (int nf = 0; nf < 8; nf++) {
                const int col = kt*128 + wk*64 + nf*8 + (lane & 3)*2;
                *(float2*)(Sbuf + (size_t)r0*SEQ + col)     = make_float2(acc[mf][nf][0], acc[mf][nf][1]);
                *(float2*)(Sbuf + (size_t)(r0+8)*SEQ + col) = make_float2(acc[mf][nf][2], acc[mf][nf][3]);
            }
            #pragma unroll
            for (int half = 0; half < 2; half++) {
                float t = -1e30f;
                #pragma unroll
                for (int nf = 0; nf < 8; nf++)
                    t = fmaxf(t, fmaxf(acc[mf][nf][half*2], acc[mf][nf][half*2+1]));
                t = fmaxf(t, __shfl_xor_sync(0xffffffffu, t, 1));
                t = fmaxf(t, __shfl_xor_sync(0xffffffffu, t, 2));
                const float mn = fmaxf(mr[mf][half], t);
                float e = 0.f;
                #pragma unroll
                for (int nf = 0; nf < 8; nf++)
                    e += __expf(acc[mf][nf][half*2] - mn) + __expf(acc[mf][nf][half*2+1] - mn);
                e += __shfl_xor_sync(0xffffffffu, e, 1);
                e += __shfl_xor_sync(0xffffffffu, e, 2);
                sr[mf][half] = sr[mf][half] * __expf(mr[mf][half] - mn) + e;
                mr[mf][half] = mn;
            }
        }
    }
    __syncthreads();
    if ((lane & 3) == 0) {
        #pragma unroll
        for (int mf = 0; mf < 2; mf++)
            #pragma unroll
            for (int half = 0; half < 2; half++) {
                const int row = wq*32 + mf*16 + (lane >> 2) + half*8;
                sMS[row][wk] = make_float2(mr[mf][half], sr[mf][half]);
            }
    }
    __syncthreads();
    if (tid < 128) {
        float2 a = sMS[tid][0], c = sMS[tid][1];
        float m = fmaxf(a.x, c.x);
        float s = a.y * __expf(a.x - m) + c.y * __expf(c.x - m);
        sFin[tid] = make_float2(m, 1.f / s);
    }
    __syncthreads();

    // -------- phase 2: P@V (kt descending), stages at s*55296 --------
    const int wd = wk;
    auto issueV = [&](int kt, int s) {
        #pragma unroll
        for (int p = 0; p < 2; p++) {
            const int row = srow8 + p*32;
            const uint32_t d = dbase + (uint32_t)s*P2_STAGE_B + 36864 + row*144 + sc16*16;
            const size_t vo = (size_t)(kt*64 + row)*128 + sc16*16;
            cp16(d,        VhG + vo);
            cp16(d + 9216, VlG + vo);
        }
    };
    auto stageP = [&](int kt, int s, const float4* pp) {
        uint32_t* Ph = dsm + s*(P2_STAGE_B/4);
        uint32_t* Pl = Ph + 4608;
        #pragma unroll
        for (int i = 0; i < 8; i++) {
            const int row = srow + i*16;
            const float2 st = sFin[row];
            float p0 = __expf(pp[i].x - st.x) * st.y;
            float p1 = __expf(pp[i].y - st.x) * st.y;
            float p2 = __expf(pp[i].z - st.x) * st.y;
            float p3 = __expf(pp[i].w - st.x) * st.y;
            __stcs((float4*)(Sbuf + (size_t)row*SEQ + kt*64 + sq4*4),
                   make_float4(p0, p1, p2, p3));
            uint32_t h0, l0, h1, l1;
            split2(p0, p1, h0, l0);
            split2(p2, p3, h1, l1);
            *(uint2*)&Ph[row*36 + sq4*2] = make_uint2(h0, h1);
            *(uint2*)&Pl[row*36 + sq4*2] = make_uint2(l0, l1);
        }
    };
    auto loadP = [&](int kt, float4* pp) {
        #pragma unroll
        for (int i = 0; i < 8; i++)
            pp[i] = *(const float4*)(Sbuf + (size_t)(srow + i*16)*SEQ + kt*64 + sq4*4);
    };

    float acc2[2][4][4];
    #pragma unroll
    for (int mf = 0; mf < 2; mf++)
        #pragma unroll
        for (int j = 0; j < 4; j++)
            #pragma unroll
            for (int q = 0; q < 4; q++) acc2[mf][j][q] = 0.f;

    const uint32_t bt_row = (uint32_t)((lane & 7) + ((lane >> 3) & 1)*8);
    const uint32_t bt_col = ((lane >> 4) & 1)*8;

    float4 pP[8];
    loadP(31, pP); stageP(31, 0, pP); issueV(31, 0); CP_COMMIT();
    loadP(30, pP); stageP(30, 1, pP); issueV(30, 1); CP_COMMIT();
    loadP(29, pP);

    for (int t = 0; t < 32; t++) {
        const int kt = 31 - t;
        CP_WAIT1();
        __syncthreads();
        if (t + 2 < 32) {
            stageP(kt - 2, (t + 2) % 3, pP);
            issueV(kt - 2, (t + 2) % 3);
            if (t + 3 < 32) loadP(kt - 3, pP);
        }
        CP_COMMIT();
        const uint32_t PhB = dbase + (uint32_t)(t % 3)*P2_STAGE_B;
        const uint32_t PlB = PhB + 18432, VhB = PhB + 36864, VlB = PhB + 46080;
        #pragma unroll
        for (int kc = 0; kc < 4; kc++) {
            uint32_t Pa[2][4], Pb[2][4];
            #pragma unroll
            for (int mf = 0; mf < 2; mf++) {
                const uint32_t ao = a_base + (uint32_t)(wq*32 + mf*16)*144 + kc*32;
                ldsm_x4(Pa[mf], PhB + ao);
                ldsm_x4(Pb[mf], PlB + ao);
            }
            #pragma unroll
            for (int sp = 0; sp < 2; sp++) {
                uint32_t Bh[4], Bl[4];
                const uint32_t boff = (uint32_t)(kc*16 + bt_row)*144
                                    + (uint32_t)(wd*32 + sp*16 + bt_col)*2;
                ldsm_x4_t(Bh, VhB + boff);
                ldsm_x4_t(Bl, VlB + boff);
                #pragma unroll
                for (int mf = 0; mf < 2; mf++) {
                    mma_bf16(acc2[mf][sp*2],   Pa[mf], Bh);   mma_bf16(acc2[mf][sp*2],   Pa[mf], Bl);
                    mma_bf16(acc2[mf][sp*2],   Pb[mf], Bh);
                    mma_bf16(acc2[mf][sp*2+1], Pa[mf], Bh+2); mma_bf16(acc2[mf][sp*2+1], Pa[mf], Bl+2);
                    mma_bf16(acc2[mf][sp*2+1], Pb[mf], Bh+2);
                }
            }
        }
    }
    #pragma unroll
    for (int mf = 0; mf < 2; mf++)
        #pragma unroll
        for (int j = 0; j < 4; j++) {
            const int col = h*64 + wd*32 + j*8 + (lane & 3)*2;
            #pragma unroll
            for (int half = 0; half < 2; half++) {
                const int q = q0 + wq*32 + mf*16 + (lane >> 2) + half*8;
                __stcs((float2*)(ctx_out + (size_t)(b*SEQ + q)*HID + col),
                       make_float2(acc2[mf][j][half*2], acc2[mf][j][half*2+1]));
            }
        }
}

// ---------------------------------------------------------------------------
extern "C" void kernel_launch(void* const* d_in, const int* in_sizes, int n_in,
                              void* d_out, int out_size)
{
    const float* X  = (const float*)d_in[0];
    const float* Wq = (const float*)d_in[1];
    const float* bq = (const float*)d_in[2];
    const float* Wk = (const float*)d_in[3];
    const float* bk = (const float*)d_in[4];
    const float* Wv = (const float*)d_in[5];
    const float* bv = (const float*)d_in[6];

    float* ctx   = (float*)d_out;
    float* probs = (float*)d_out + (size_t)BATCH * SEQ * HID;

    cudaFuncSetAttribute(qkv_t_kernel, cudaFuncAttributeMaxDynamicSharedMemorySize, QKV_DSMEM);
    cudaFuncSetAttribute(attn_fused_kernel, cudaFuncAttributeMaxDynamicSharedMemorySize, ATTN_DSMEM);

    const int nTot4 = (MTOT * HID + 3 * HID * HID) / 4;
    split_all_kernel<<<nTot4 / 256, 256>>>(X, Wq, Wk, Wv);

    dim3 qkv_grid(HID/128, MTOT/128, 3);
    qkv_t_kernel<<<qkv_grid, 256, QKV_DSMEM>>>(bq, bk, bv);

    dim3 att_grid(SEQ/128, BH);
    attn_fused_kernel<<<att_grid, 256, ATTN_DSMEM>>>(ctx, probs);
}